// round 2
// baseline (speedup 1.0000x reference)
#include <cuda_runtime.h>
#include <math.h>

// Problem constants (B=4, H=16, S=1024, D=64, fp32)
#define S_LEN 1024
#define D_DIM 64
#define BH_N  64          // B*H
#define QT    16          // q rows per block
#define KTILE 256         // k columns per QK smem tile
#define VTILE 64          // k rows per PV smem tile
#define NT    256         // threads per block

#define QSTR  68          // Q tile row stride (floats), 16B-aligned, padded
#define KTSTR 257         // transposed K tile row stride: KT^T[d][k], conflict-free
#define VSTR  68          // V tile row stride

// shared memory layout (floats)
#define SS_OFF   0
#define SS_SIZE  (QT * S_LEN)            // 16384 floats: full 16x1024 score block
#define KV_OFF   (SS_OFF + SS_SIZE)
#define KV_SIZE  (D_DIM * KTSTR)         // 16448 floats: K^T tile (V tile fits inside)
#define Q_OFF    (KV_OFF + KV_SIZE)
#define Q_SIZE   (QT * QSTR)             // 1088 floats
#define SMEM_FLOATS (Q_OFF + Q_SIZE)
#define SMEM_BYTES  (SMEM_FLOATS * 4)    // 135,680 bytes

__global__ void __launch_bounds__(NT, 1)
attn_fp32_kernel(const float* __restrict__ Q, const float* __restrict__ K,
                 const float* __restrict__ V, const float* __restrict__ Bias,
                 float* __restrict__ Out, float* __restrict__ Wout)
{
    extern __shared__ float sm[];
    float* Ss = sm + SS_OFF;   // [QT][S_LEN]
    float* KV = sm + KV_OFF;   // K^T tile [D][KTSTR] or V tile [VTILE][VSTR]
    float* Qs = sm + Q_OFF;    // [QT][QSTR]

    const int t  = threadIdx.x;
    const int qt = blockIdx.x;     // 0..63
    const int bh = blockIdx.y;     // 0..63

    const float* Qg = Q + ((size_t)bh * S_LEN + (size_t)qt * QT) * D_DIM;
    const float* Kg = K + (size_t)bh * S_LEN * D_DIM;
    const float* Vg = V + (size_t)bh * S_LEN * D_DIM;

    // ---- load Q tile (16x64 floats, one float4 per thread, coalesced) ----
    {
        int r = t >> 4;               // 0..15
        int d4 = (t & 15) << 2;       // 0..60
        *(float4*)&Qs[r * QSTR + d4] = *(const float4*)&Qg[r * D_DIM + d4];
    }

    const int qg = t >> 6;   // 0..3 : q-row group (rows qg*4 .. qg*4+3), uniform per warp
    const int kc = t & 63;   // 0..63 : k column within tile (lane-consecutive)

    // =========================== Phase 1: S = Q K^T * scale ===========================
    for (int kt = 0; kt < S_LEN / KTILE; ++kt) {
        __syncthreads();
        // load K tile transposed into smem: KV[d][k], 256 rows of K, 64 d each
        #pragma unroll
        for (int i = 0; i < 16; ++i) {
            int f  = t + i * NT;            // 0..4095 float4 chunks
            int r  = f >> 4;                // 0..255 (k row in tile)
            int d4 = (f & 15) << 2;         // 0..60
            float4 kv4 = *(const float4*)&Kg[((size_t)kt * KTILE + r) * D_DIM + d4];
            KV[(d4 + 0) * KTSTR + r] = kv4.x;
            KV[(d4 + 1) * KTSTR + r] = kv4.y;
            KV[(d4 + 2) * KTSTR + r] = kv4.z;
            KV[(d4 + 3) * KTSTR + r] = kv4.w;
        }
        __syncthreads();

        float acc[4][4];
        #pragma unroll
        for (int a = 0; a < 4; ++a)
            #pragma unroll
            for (int b = 0; b < 4; ++b) acc[a][b] = 0.f;

        #pragma unroll
        for (int d = 0; d < D_DIM; ++d) {
            float rq[4], rk[4];
            #pragma unroll
            for (int iq = 0; iq < 4; ++iq)       // broadcast within warp
                rq[iq] = Qs[(qg * 4 + iq) * QSTR + d];
            #pragma unroll
            for (int ik = 0; ik < 4; ++ik)       // conflict-free: (d + kc) mod 32 distinct
                rk[ik] = KV[d * KTSTR + kc + 64 * ik];
            #pragma unroll
            for (int iq = 0; iq < 4; ++iq)
                #pragma unroll
                for (int ik = 0; ik < 4; ++ik)
                    acc[iq][ik] = fmaf(rq[iq], rk[ik], acc[iq][ik]);
        }

        #pragma unroll
        for (int iq = 0; iq < 4; ++iq)
            #pragma unroll
            for (int ik = 0; ik < 4; ++ik)
                Ss[(qg * 4 + iq) * S_LEN + kt * KTILE + kc + 64 * ik] =
                    acc[iq][ik] * 0.125f;   // 1/sqrt(64)
    }
    __syncthreads();

    // ======================= Phase 2: softmax(S + bias) per row =======================
    {
        const int w = t >> 5, lane = t & 31;
        #pragma unroll
        for (int rr = 0; rr < 2; ++rr) {
            int row   = w * 2 + rr;            // 0..15
            int qglob = qt * QT + row;
            const float* brow = Bias + (size_t)qglob * S_LEN;
            float v[32];
            float m = -INFINITY;
            #pragma unroll
            for (int j = 0; j < 32; ++j) {
                v[j] = Ss[row * S_LEN + lane + 32 * j] + brow[lane + 32 * j];
                m = fmaxf(m, v[j]);
            }
            #pragma unroll
            for (int o = 16; o; o >>= 1) m = fmaxf(m, __shfl_xor_sync(0xffffffffu, m, o));
            float sum = 0.f;
            #pragma unroll
            for (int j = 0; j < 32; ++j) { v[j] = __expf(v[j] - m); sum += v[j]; }
            #pragma unroll
            for (int o = 16; o; o >>= 1) sum += __shfl_xor_sync(0xffffffffu, sum, o);
            float inv = 1.f / sum;
            float* wrow = Wout + (size_t)bh * S_LEN * S_LEN + (size_t)qglob * S_LEN;
            #pragma unroll
            for (int j = 0; j < 32; ++j) {
                float wv = v[j] * inv;
                Ss[row * S_LEN + lane + 32 * j] = wv;   // keep for PV
                wrow[lane + 32 * j] = wv;               // attn_weights output (coalesced)
            }
        }
    }

    // =============================== Phase 3: O = W V ================================
    const int dcol = t & 63;
    float oacc[4] = {0.f, 0.f, 0.f, 0.f};
    for (int vt = 0; vt < S_LEN / VTILE; ++vt) {
        __syncthreads();   // first iter also orders Phase2 Ss writes vs Phase3 reads
        #pragma unroll
        for (int i = 0; i < 4; ++i) {
            int f  = t + i * NT;           // 0..1023 float4 chunks
            int r  = f >> 4;               // 0..63
            int d4 = (f & 15) << 2;
            *(float4*)&KV[r * VSTR + d4] =
                *(const float4*)&Vg[((size_t)vt * VTILE + r) * D_DIM + d4];
        }
        __syncthreads();
        #pragma unroll
        for (int k4 = 0; k4 < VTILE / 4; ++k4) {
            float rv[4];
            #pragma unroll
            for (int j = 0; j < 4; ++j)    // conflict-free: (4k + dcol) mod 32 distinct
                rv[j] = KV[(k4 * 4 + j) * VSTR + dcol];
            #pragma unroll
            for (int iq = 0; iq < 4; ++iq) {
                float4 rw = *(const float4*)&Ss[(qg * 4 + iq) * S_LEN + vt * VTILE + k4 * 4];
                oacc[iq] = fmaf(rw.x, rv[0], oacc[iq]);
                oacc[iq] = fmaf(rw.y, rv[1], oacc[iq]);
                oacc[iq] = fmaf(rw.z, rv[2], oacc[iq]);
                oacc[iq] = fmaf(rw.w, rv[3], oacc[iq]);
            }
        }
    }
    #pragma unroll
    for (int iq = 0; iq < 4; ++iq)
        Out[((size_t)bh * S_LEN + (size_t)qt * QT + qg * 4 + iq) * D_DIM + dcol] = oacc[iq];
}

extern "C" void kernel_launch(void* const* d_in, const int* in_sizes, int n_in,
                              void* d_out, int out_size)
{
    const float* Q    = (const float*)d_in[0];
    const float* K    = (const float*)d_in[1];
    const float* V    = (const float*)d_in[2];
    const float* Bias = (const float*)d_in[3];

    float* Out  = (float*)d_out;
    float* Wout = Out + (size_t)BH_N * S_LEN * D_DIM;   // tuple: (output, attn_weights)

    cudaFuncSetAttribute(attn_fp32_kernel,
                         cudaFuncAttributeMaxDynamicSharedMemorySize, SMEM_BYTES);

    dim3 grid(S_LEN / QT, BH_N);   // (64, 64) = 4096 blocks
    attn_fp32_kernel<<<grid, NT, SMEM_BYTES>>>(Q, K, V, Bias, Out, Wout);
}